// round 14
// baseline (speedup 1.0000x reference)
#include <cuda_runtime.h>

// Stain normalization: out = clip(exp(-((-log(x+1e-6)) @ M * gamma + beta)), 0, 1)
// Algebraically folded: out = sat(exp( log(x+1e-6) @ C - beta )), C[c][d] = M[c][d]*gamma[d]
//
// FINAL FORM. Identical source measured 63.49 / 62.43 / 63.55 / 63.07 / 62.98 /
// 63.55 / 63.52 us across seven runs (mean 63.2, sigma ~0.4): the workload sits
// at the sustained HBM mixed read+write floor -- 403 MB irreducible fp32
// traffic at ~6.4 TB/s effective steady-state (LTS chip cap ~6300 B/cyc,
// path-independent). Tested and rejected: direct strided LDG/STG (neutral),
// TMA bulk load+store (best ncu-internal 55.7us/78.3% DRAM, same wall),
// persistent triple-buffered TMA pipeline (70.4us regression: MLP/occupancy
// collapse at 3 CTAs/SM), TMA+multi-thread stcs (64.3us), 256-bit v8 ld/st
// (65.9us regression: regs 32->42, occ 92->57%). Compute pipes ~26% -- not
// binding. No unexploited axis remains.
//
// Structure: coalesced 128-bit streaming global loads -> smem; in-place compute
// with conflict-free stride-12 LDS.128 (banks 12t mod 32 distinct per 8-lane
// phase); coalesced 128-bit streaming stores. 12 KB smem, 256 threads, ~8 CTAs/SM.

constexpr int TPB = 256;
constexpr int F4_PER_THREAD = 3;                  // 12 floats = 4 pixels per thread
constexpr int F4_PER_BLOCK = TPB * F4_PER_THREAD; // 768 float4 = 12 KB

__global__ __launch_bounds__(TPB)
void stain_norm_smem_kernel(const float4* __restrict__ x4,
                            const float*  __restrict__ M,      // 3x3 row-major
                            const float*  __restrict__ gamma,  // 3
                            const float*  __restrict__ beta,   // 3
                            float4* __restrict__ out4,
                            int n_groups)                      // 4-pixel groups total
{
    __shared__ float4 s[F4_PER_BLOCK];

    const int group_base = blockIdx.x * TPB;          // first group of this block
    const int f4_base    = group_base * 3;            // first float4 of this block
    const int n_f4       = n_groups * 3;              // total float4 count

    // ---- Load phase: fully coalesced streaming loads ----
    #pragma unroll
    for (int k = 0; k < F4_PER_THREAD; ++k) {
        int idx = k * TPB + threadIdx.x;
        int g = f4_base + idx;
        if (g < n_f4) s[idx] = __ldcs(&x4[g]);
    }
    __syncthreads();

    // ---- Compute phase (in place; each thread's 12 floats are private) ----
    if (group_base + threadIdx.x < n_groups) {
        // Broadcast constants; fold gamma into M, negate beta.
        float g0 = __ldg(&gamma[0]), g1 = __ldg(&gamma[1]), g2 = __ldg(&gamma[2]);
        float c00 = __ldg(&M[0]) * g0, c01 = __ldg(&M[1]) * g1, c02 = __ldg(&M[2]) * g2;
        float c10 = __ldg(&M[3]) * g0, c11 = __ldg(&M[4]) * g1, c12 = __ldg(&M[5]) * g2;
        float c20 = __ldg(&M[6]) * g0, c21 = __ldg(&M[7]) * g1, c22 = __ldg(&M[8]) * g2;
        float nb0 = -__ldg(&beta[0]), nb1 = -__ldg(&beta[1]), nb2 = -__ldg(&beta[2]);

        float4 va = s[3 * threadIdx.x + 0];
        float4 vb = s[3 * threadIdx.x + 1];
        float4 vc = s[3 * threadIdx.x + 2];

        float in[12] = { va.x, va.y, va.z, va.w,
                         vb.x, vb.y, vb.z, vb.w,
                         vc.x, vc.y, vc.z, vc.w };
        float ov[12];

        #pragma unroll
        for (int p = 0; p < 4; ++p) {
            // l = log(x + 1e-6)   (negation folded into the exp sign)
            float l0 = __logf(in[3 * p + 0] + 1e-6f);
            float l1 = __logf(in[3 * p + 1] + 1e-6f);
            float l2 = __logf(in[3 * p + 2] + 1e-6f);

            // u_d = l0*C0d + l1*C1d + l2*C2d - beta_d ;  out = sat(exp(u_d))
            float u0 = fmaf(l0, c00, fmaf(l1, c10, fmaf(l2, c20, nb0)));
            float u1 = fmaf(l0, c01, fmaf(l1, c11, fmaf(l2, c21, nb1)));
            float u2 = fmaf(l0, c02, fmaf(l1, c12, fmaf(l2, c22, nb2)));

            ov[3 * p + 0] = __saturatef(__expf(u0));
            ov[3 * p + 1] = __saturatef(__expf(u1));
            ov[3 * p + 2] = __saturatef(__expf(u2));
        }

        s[3 * threadIdx.x + 0] = make_float4(ov[0], ov[1], ov[2],  ov[3]);
        s[3 * threadIdx.x + 1] = make_float4(ov[4], ov[5], ov[6],  ov[7]);
        s[3 * threadIdx.x + 2] = make_float4(ov[8], ov[9], ov[10], ov[11]);
    }
    __syncthreads();

    // ---- Store phase: fully coalesced, streaming (evict-first) ----
    #pragma unroll
    for (int k = 0; k < F4_PER_THREAD; ++k) {
        int idx = k * TPB + threadIdx.x;
        int g = f4_base + idx;
        if (g < n_f4) __stcs(&out4[g], s[idx]);
    }
}

// Scalar tail for leftover elements (n_elem not divisible by 12).
__global__ void stain_norm_tail_kernel(const float* __restrict__ x,
                                       const float* __restrict__ M,
                                       const float* __restrict__ gamma,
                                       const float* __restrict__ beta,
                                       float* __restrict__ out,
                                       int start_elem, int n_elem)
{
    int e = start_elem + blockIdx.x * blockDim.x + threadIdx.x;
    if (e >= n_elem) return;
    int pix = e / 3;
    int d = e - pix * 3;
    float l0 = __logf(x[pix * 3 + 0] + 1e-6f);
    float l1 = __logf(x[pix * 3 + 1] + 1e-6f);
    float l2 = __logf(x[pix * 3 + 2] + 1e-6f);
    float gd = __ldg(&gamma[d]);
    float u = fmaf(l0, __ldg(&M[0 * 3 + d]) * gd,
             fmaf(l1, __ldg(&M[1 * 3 + d]) * gd,
             fmaf(l2, __ldg(&M[2 * 3 + d]) * gd, -__ldg(&beta[d]))));
    out[e] = __saturatef(__expf(u));
}

extern "C" void kernel_launch(void* const* d_in, const int* in_sizes, int n_in,
                              void* d_out, int out_size)
{
    const float* x     = (const float*)d_in[0];
    const float* M     = (const float*)d_in[1];
    const float* gamma = (const float*)d_in[2];
    const float* beta  = (const float*)d_in[3];
    float* out = (float*)d_out;

    int n_elem = in_sizes[0];            // total floats (B*H*W*3)
    int n_groups = n_elem / 12;          // 4-pixel (12-float) groups

    if (n_groups > 0) {
        int blocks = (n_groups + TPB - 1) / TPB;
        stain_norm_smem_kernel<<<blocks, TPB>>>(
            (const float4*)x, M, gamma, beta, (float4*)out, n_groups);
    }

    int done = n_groups * 12;
    int rem = n_elem - done;
    if (rem > 0) {
        int threads = 256;
        int blocks = (rem + threads - 1) / threads;
        stain_norm_tail_kernel<<<blocks, threads>>>(x, M, gamma, beta, out, done, n_elem);
    }
}

// round 15
// speedup vs baseline: 1.0122x; 1.0122x over previous
#include <cuda_runtime.h>

// Stain normalization: out = clip(exp(-((-log(x+1e-6)) @ M * gamma + beta)), 0, 1)
// Algebraically folded: out = sat(exp( log(x+1e-6) @ C - beta )), C[c][d] = M[c][d]*gamma[d]
//
// FINAL FORM. Identical source measured 63.49 / 62.43 / 63.55 / 63.07 / 62.98 /
// 63.55 / 63.52 / 63.52 us across eight runs (mean 63.2, sigma ~0.4): the
// workload sits at the sustained HBM mixed read+write floor -- 403 MB
// irreducible fp32 traffic at ~6.4 TB/s effective steady-state (LTS chip cap
// ~6300 B/cyc, path-independent). Tested and rejected: direct strided LDG/STG
// (neutral), TMA bulk load+store (best ncu-internal 55.7us/78.3% DRAM, same
// wall), persistent triple-buffered TMA pipeline (70.4us regression:
// MLP/occupancy collapse at 3 CTAs/SM), TMA+multi-thread stcs (64.3us),
// 256-bit v8 ld/st (65.9us regression: regs 32->42, occ 92->57%). Compute
// pipes ~26% -- not binding. No unexploited axis remains.
//
// Structure: coalesced 128-bit streaming global loads -> smem; in-place compute
// with conflict-free stride-12 LDS.128 (banks 12t mod 32 distinct per 8-lane
// phase); coalesced 128-bit streaming stores. 12 KB smem, 256 threads, ~8 CTAs/SM.

constexpr int TPB = 256;
constexpr int F4_PER_THREAD = 3;                  // 12 floats = 4 pixels per thread
constexpr int F4_PER_BLOCK = TPB * F4_PER_THREAD; // 768 float4 = 12 KB

__global__ __launch_bounds__(TPB)
void stain_norm_smem_kernel(const float4* __restrict__ x4,
                            const float*  __restrict__ M,      // 3x3 row-major
                            const float*  __restrict__ gamma,  // 3
                            const float*  __restrict__ beta,   // 3
                            float4* __restrict__ out4,
                            int n_groups)                      // 4-pixel groups total
{
    __shared__ float4 s[F4_PER_BLOCK];

    const int group_base = blockIdx.x * TPB;          // first group of this block
    const int f4_base    = group_base * 3;            // first float4 of this block
    const int n_f4       = n_groups * 3;              // total float4 count

    // ---- Load phase: fully coalesced streaming loads ----
    #pragma unroll
    for (int k = 0; k < F4_PER_THREAD; ++k) {
        int idx = k * TPB + threadIdx.x;
        int g = f4_base + idx;
        if (g < n_f4) s[idx] = __ldcs(&x4[g]);
    }
    __syncthreads();

    // ---- Compute phase (in place; each thread's 12 floats are private) ----
    if (group_base + threadIdx.x < n_groups) {
        // Broadcast constants; fold gamma into M, negate beta.
        float g0 = __ldg(&gamma[0]), g1 = __ldg(&gamma[1]), g2 = __ldg(&gamma[2]);
        float c00 = __ldg(&M[0]) * g0, c01 = __ldg(&M[1]) * g1, c02 = __ldg(&M[2]) * g2;
        float c10 = __ldg(&M[3]) * g0, c11 = __ldg(&M[4]) * g1, c12 = __ldg(&M[5]) * g2;
        float c20 = __ldg(&M[6]) * g0, c21 = __ldg(&M[7]) * g1, c22 = __ldg(&M[8]) * g2;
        float nb0 = -__ldg(&beta[0]), nb1 = -__ldg(&beta[1]), nb2 = -__ldg(&beta[2]);

        float4 va = s[3 * threadIdx.x + 0];
        float4 vb = s[3 * threadIdx.x + 1];
        float4 vc = s[3 * threadIdx.x + 2];

        float in[12] = { va.x, va.y, va.z, va.w,
                         vb.x, vb.y, vb.z, vb.w,
                         vc.x, vc.y, vc.z, vc.w };
        float ov[12];

        #pragma unroll
        for (int p = 0; p < 4; ++p) {
            // l = log(x + 1e-6)   (negation folded into the exp sign)
            float l0 = __logf(in[3 * p + 0] + 1e-6f);
            float l1 = __logf(in[3 * p + 1] + 1e-6f);
            float l2 = __logf(in[3 * p + 2] + 1e-6f);

            // u_d = l0*C0d + l1*C1d + l2*C2d - beta_d ;  out = sat(exp(u_d))
            float u0 = fmaf(l0, c00, fmaf(l1, c10, fmaf(l2, c20, nb0)));
            float u1 = fmaf(l0, c01, fmaf(l1, c11, fmaf(l2, c21, nb1)));
            float u2 = fmaf(l0, c02, fmaf(l1, c12, fmaf(l2, c22, nb2)));

            ov[3 * p + 0] = __saturatef(__expf(u0));
            ov[3 * p + 1] = __saturatef(__expf(u1));
            ov[3 * p + 2] = __saturatef(__expf(u2));
        }

        s[3 * threadIdx.x + 0] = make_float4(ov[0], ov[1], ov[2],  ov[3]);
        s[3 * threadIdx.x + 1] = make_float4(ov[4], ov[5], ov[6],  ov[7]);
        s[3 * threadIdx.x + 2] = make_float4(ov[8], ov[9], ov[10], ov[11]);
    }
    __syncthreads();

    // ---- Store phase: fully coalesced, streaming (evict-first) ----
    #pragma unroll
    for (int k = 0; k < F4_PER_THREAD; ++k) {
        int idx = k * TPB + threadIdx.x;
        int g = f4_base + idx;
        if (g < n_f4) __stcs(&out4[g], s[idx]);
    }
}

// Scalar tail for leftover elements (n_elem not divisible by 12).
__global__ void stain_norm_tail_kernel(const float* __restrict__ x,
                                       const float* __restrict__ M,
                                       const float* __restrict__ gamma,
                                       const float* __restrict__ beta,
                                       float* __restrict__ out,
                                       int start_elem, int n_elem)
{
    int e = start_elem + blockIdx.x * blockDim.x + threadIdx.x;
    if (e >= n_elem) return;
    int pix = e / 3;
    int d = e - pix * 3;
    float l0 = __logf(x[pix * 3 + 0] + 1e-6f);
    float l1 = __logf(x[pix * 3 + 1] + 1e-6f);
    float l2 = __logf(x[pix * 3 + 2] + 1e-6f);
    float gd = __ldg(&gamma[d]);
    float u = fmaf(l0, __ldg(&M[0 * 3 + d]) * gd,
             fmaf(l1, __ldg(&M[1 * 3 + d]) * gd,
             fmaf(l2, __ldg(&M[2 * 3 + d]) * gd, -__ldg(&beta[d]))));
    out[e] = __saturatef(__expf(u));
}

extern "C" void kernel_launch(void* const* d_in, const int* in_sizes, int n_in,
                              void* d_out, int out_size)
{
    const float* x     = (const float*)d_in[0];
    const float* M     = (const float*)d_in[1];
    const float* gamma = (const float*)d_in[2];
    const float* beta  = (const float*)d_in[3];
    float* out = (float*)d_out;

    int n_elem = in_sizes[0];            // total floats (B*H*W*3)
    int n_groups = n_elem / 12;          // 4-pixel (12-float) groups

    if (n_groups > 0) {
        int blocks = (n_groups + TPB - 1) / TPB;
        stain_norm_smem_kernel<<<blocks, TPB>>>(
            (const float4*)x, M, gamma, beta, (float4*)out, n_groups);
    }

    int done = n_groups * 12;
    int rem = n_elem - done;
    if (rem > 0) {
        int threads = 256;
        int blocks = (rem + threads - 1) / threads;
        stain_norm_tail_kernel<<<blocks, threads>>>(x, M, gamma, beta, out, done, n_elem);
    }
}